// round 13
// baseline (speedup 1.0000x reference)
#include <cuda_runtime.h>
#include <cuda_bf16.h>

#define T_BINS 16384
#define EDGE   4
#define WIN    9      // 2*EDGE+1
#define D_DIM  128    // 32 float4 per row

#define WARPS_PER_BLK 4   // 128-thread blocks

// TWO samples per warp. Lane l owns output floats [4l,4l+4) of both samples.
//
// Analytic bin math (no table loads): edges are i * 2^-14, exact in fp32:
//   xi = x*16384 exact; i = floor(xi); argmax tie (x exactly on an interior
//   edge <=> xi == (float)i) resolves to the LOWER bin; and
//   d0 = (x - et[i]) / wide == xi - (i + 0.5) bit-exactly.
//
// ILP plan: one LDG.64 fetches both x values; batch-1 gathers for BOTH
// samples (5+5 LDG.128 = 40 payload regs) fly in one L2 round trip, then
// batch-2 (4+4). Per-warp round trips ~3 now cover 2 samples, halving
// exposed latency per sample vs the 1-sample/warp kernel. 4096 warps =
// 28/SM -> one wave at <=72 regs (__launch_bounds__(128,7)).
//
// Weights: lanes 0..8 compute sample A's exps, lanes 16..24 sample B's,
// in ONE predicated __expf; 16-wide xor-butterfly reduces each half.
__global__ void __launch_bounds__(128, 7)
hwnet_kernel(const float* __restrict__ xin,
             const float* __restrict__ vt,
             float* __restrict__ out,
             int B)
{
    int w    = (int)((blockIdx.x * blockDim.x + threadIdx.x) >> 5);
    int lane = (int)(threadIdx.x & 31);
    int nPairs = (B + 1) >> 1;
    if (w >= nPairs) return;

    int sA = 2 * w;
    int sB = 2 * w + 1;
    bool hasB = (sB < B);

    // Both x values in one LDG.64 (B assumed even-aligned allocation; if B
    // is odd the tail warp reads one extra in-bounds-allocated float -- guard
    // by falling back to scalar loads in that case).
    float xA, xB;
    if (hasB) {
        float2 xx = __ldg(&((const float2*)xin)[w]);
        xA = xx.x; xB = xx.y;
    } else {
        xA = __ldg(&xin[sA]); xB = xA;
    }

    // ---- analytic bin index + normalized distance, per sample ----
    float xiA = xA * (float)T_BINS;
    int   iA  = min((int)xiA, T_BINS - 1);
    if (iA > 0 && (float)iA == xiA) --iA;               // argmax tie -> lower
    int   icA = min(max(iA, EDGE), T_BINS - 1 - EDGE);

    float xiB = xB * (float)T_BINS;
    int   iB  = min((int)xiB, T_BINS - 1);
    if (iB > 0 && (float)iB == xiB) --iB;
    int   icB = min(max(iB, EDGE), T_BINS - 1 - EDGE);

    const float4* vt4 = (const float4*)vt;
    unsigned rowA = (unsigned)(icA - EDGE) * 32u + (unsigned)lane;
    unsigned rowB = (unsigned)(icB - EDGE) * 32u + (unsigned)lane;

    // ---- batch 1: 5 rows of A + 5 rows of B, one flight ----
    float4 a0 = __ldg(&vt4[rowA]);
    float4 a1 = __ldg(&vt4[rowA + 32]);
    float4 a2 = __ldg(&vt4[rowA + 64]);
    float4 a3 = __ldg(&vt4[rowA + 96]);
    float4 a4 = __ldg(&vt4[rowA + 128]);
    float4 b0 = __ldg(&vt4[rowB]);
    float4 b1 = __ldg(&vt4[rowB + 32]);
    float4 b2 = __ldg(&vt4[rowB + 64]);
    float4 b3 = __ldg(&vt4[rowB + 96]);
    float4 b4 = __ldg(&vt4[rowB + 128]);

    // ---- softmax weights for BOTH samples, overlapped with the flight ----
    // d0 = xi - (i + 0.5) is bit-exact vs reference; base = d0 - (ic - i).
    float baseA = (xiA - ((float)iA + 0.5f)) - (float)(icA - iA);
    float baseB = (xiB - ((float)iB + 0.5f)) - (float)(icB - iB);

    int  lw = lane & 15;
    float e = 0.0f;
    if (lw < WIN) {
        float base = (lane < 16) ? baseA : baseB;
        float d = base - (float)(lw - EDGE);
        e = __expf(-10.0f * d * d);                     // max term >= e^-2.5
    }
    float s = e;                                        // 16-wide butterfly:
    #pragma unroll                                      // sums each half-warp
    for (int off = 8; off > 0; off >>= 1)
        s += __shfl_xor_sync(0xffffffffu, s, off);
    float invA = 1.0f / __shfl_sync(0xffffffffu, s, 0);
    float invB = 1.0f / __shfl_sync(0xffffffffu, s, 16);

    float4 accA, accB;
    {
        float t = __shfl_sync(0xffffffffu, e, 0) * invA;
        accA.x = a0.x * t; accA.y = a0.y * t; accA.z = a0.z * t; accA.w = a0.w * t;
        t = __shfl_sync(0xffffffffu, e, 1) * invA;
        accA.x = fmaf(a1.x, t, accA.x); accA.y = fmaf(a1.y, t, accA.y);
        accA.z = fmaf(a1.z, t, accA.z); accA.w = fmaf(a1.w, t, accA.w);
        t = __shfl_sync(0xffffffffu, e, 2) * invA;
        accA.x = fmaf(a2.x, t, accA.x); accA.y = fmaf(a2.y, t, accA.y);
        accA.z = fmaf(a2.z, t, accA.z); accA.w = fmaf(a2.w, t, accA.w);
        t = __shfl_sync(0xffffffffu, e, 3) * invA;
        accA.x = fmaf(a3.x, t, accA.x); accA.y = fmaf(a3.y, t, accA.y);
        accA.z = fmaf(a3.z, t, accA.z); accA.w = fmaf(a3.w, t, accA.w);
        t = __shfl_sync(0xffffffffu, e, 4) * invA;
        accA.x = fmaf(a4.x, t, accA.x); accA.y = fmaf(a4.y, t, accA.y);
        accA.z = fmaf(a4.z, t, accA.z); accA.w = fmaf(a4.w, t, accA.w);
    }
    {
        float t = __shfl_sync(0xffffffffu, e, 16) * invB;
        accB.x = b0.x * t; accB.y = b0.y * t; accB.z = b0.z * t; accB.w = b0.w * t;
        t = __shfl_sync(0xffffffffu, e, 17) * invB;
        accB.x = fmaf(b1.x, t, accB.x); accB.y = fmaf(b1.y, t, accB.y);
        accB.z = fmaf(b1.z, t, accB.z); accB.w = fmaf(b1.w, t, accB.w);
        t = __shfl_sync(0xffffffffu, e, 18) * invB;
        accB.x = fmaf(b2.x, t, accB.x); accB.y = fmaf(b2.y, t, accB.y);
        accB.z = fmaf(b2.z, t, accB.z); accB.w = fmaf(b2.w, t, accB.w);
        t = __shfl_sync(0xffffffffu, e, 19) * invB;
        accB.x = fmaf(b3.x, t, accB.x); accB.y = fmaf(b3.y, t, accB.y);
        accB.z = fmaf(b3.z, t, accB.z); accB.w = fmaf(b3.w, t, accB.w);
        t = __shfl_sync(0xffffffffu, e, 20) * invB;
        accB.x = fmaf(b4.x, t, accB.x); accB.y = fmaf(b4.y, t, accB.y);
        accB.z = fmaf(b4.z, t, accB.z); accB.w = fmaf(b4.w, t, accB.w);
    }

    // ---- batch 2: remaining 4 rows of each (regs from batch 1 now free) ----
    float4 a5 = __ldg(&vt4[rowA + 160]);
    float4 a6 = __ldg(&vt4[rowA + 192]);
    float4 a7 = __ldg(&vt4[rowA + 224]);
    float4 a8 = __ldg(&vt4[rowA + 256]);
    float4 b5 = __ldg(&vt4[rowB + 160]);
    float4 b6 = __ldg(&vt4[rowB + 192]);
    float4 b7 = __ldg(&vt4[rowB + 224]);
    float4 b8 = __ldg(&vt4[rowB + 256]);

    {
        float t = __shfl_sync(0xffffffffu, e, 5) * invA;
        accA.x = fmaf(a5.x, t, accA.x); accA.y = fmaf(a5.y, t, accA.y);
        accA.z = fmaf(a5.z, t, accA.z); accA.w = fmaf(a5.w, t, accA.w);
        t = __shfl_sync(0xffffffffu, e, 6) * invA;
        accA.x = fmaf(a6.x, t, accA.x); accA.y = fmaf(a6.y, t, accA.y);
        accA.z = fmaf(a6.z, t, accA.z); accA.w = fmaf(a6.w, t, accA.w);
        t = __shfl_sync(0xffffffffu, e, 7) * invA;
        accA.x = fmaf(a7.x, t, accA.x); accA.y = fmaf(a7.y, t, accA.y);
        accA.z = fmaf(a7.z, t, accA.z); accA.w = fmaf(a7.w, t, accA.w);
        t = __shfl_sync(0xffffffffu, e, 8) * invA;
        accA.x = fmaf(a8.x, t, accA.x); accA.y = fmaf(a8.y, t, accA.y);
        accA.z = fmaf(a8.z, t, accA.z); accA.w = fmaf(a8.w, t, accA.w);
    }
    {
        float t = __shfl_sync(0xffffffffu, e, 21) * invB;
        accB.x = fmaf(b5.x, t, accB.x); accB.y = fmaf(b5.y, t, accB.y);
        accB.z = fmaf(b5.z, t, accB.z); accB.w = fmaf(b5.w, t, accB.w);
        t = __shfl_sync(0xffffffffu, e, 22) * invB;
        accB.x = fmaf(b6.x, t, accB.x); accB.y = fmaf(b6.y, t, accB.y);
        accB.z = fmaf(b6.z, t, accB.z); accB.w = fmaf(b6.w, t, accB.w);
        t = __shfl_sync(0xffffffffu, e, 23) * invB;
        accB.x = fmaf(b7.x, t, accB.x); accB.y = fmaf(b7.y, t, accB.y);
        accB.z = fmaf(b7.z, t, accB.z); accB.w = fmaf(b7.w, t, accB.w);
        t = __shfl_sync(0xffffffffu, e, 24) * invB;
        accB.x = fmaf(b8.x, t, accB.x); accB.y = fmaf(b8.y, t, accB.y);
        accB.z = fmaf(b8.z, t, accB.z); accB.w = fmaf(b8.w, t, accB.w);
    }

    float4* out4 = (float4*)out;
    out4[(size_t)sA * 32 + lane] = accA;
    if (hasB) out4[(size_t)sB * 32 + lane] = accB;
}

extern "C" void kernel_launch(void* const* d_in, const int* in_sizes, int n_in,
                              void* d_out, int out_size)
{
    // metadata order: inputs [B,1], evaluate_table [T,1], evaluate_min_table [T,1],
    //                 evaluate_max_table [T,1], vector_table [T,D]
    const float* xin = (const float*)d_in[0];
    const float* vt  = (const float*)d_in[4];
    float* out = (float*)d_out;

    int B = in_sizes[0];                         // 8192
    int nPairs  = (B + 1) / 2;                   // 4096 warps
    int threads = 32 * WARPS_PER_BLK;            // 128
    int blocks  = (nPairs + WARPS_PER_BLK - 1) / WARPS_PER_BLK;

    hwnet_kernel<<<blocks, threads>>>(xin, vt, out, B);
}